// round 10
// baseline (speedup 1.0000x reference)
#include <cuda_runtime.h>
#include <cuda_fp16.h>
#include <math.h>
#include <cstdint>

#define BB   2
#define LL   4096
#define DD   1024
#define NH   16
#define HDIM 64
#define BSZ  256
#define NBLK (LL / BSZ)     // 16
#define MR   (BB * LL)      // 8192

// Scratch (allocation-free, __device__ globals) — all fp16
__device__ __half g_Qh[BB * NH * LL * HDIM];
__device__ __half g_Kh[BB * NH * LL * HDIM];
__device__ __half g_Vh[BB * NH * LL * HDIM];
__device__ __half g_Oh[MR * DD];
__device__ __half g_Xh[MR * DD];
__device__ __half g_Wqkvh[3 * DD * DD];
__device__ __half g_Wouth[DD * DD];

// ---------------------------------------------------------------------------
// helpers
// ---------------------------------------------------------------------------
__device__ __forceinline__ uint32_t smem_u32(const void* p) {
    uint32_t a;
    asm("{ .reg .u64 t; cvta.to.shared.u64 t, %1; cvt.u32.u64 %0, t; }" : "=r"(a) : "l"(p));
    return a;
}
__device__ __forceinline__ void cp16(void* smem_dst, const void* gmem_src) {
    unsigned s = (unsigned)__cvta_generic_to_shared(smem_dst);
    asm volatile("cp.async.cg.shared.global [%0], [%1], 16;\n" :: "r"(s), "l"(gmem_src));
}
__device__ __forceinline__ void cp_commit() { asm volatile("cp.async.commit_group;\n"); }
template <int N>
__device__ __forceinline__ void cp_wait() { asm volatile("cp.async.wait_group %0;\n" :: "n"(N)); }

__device__ __forceinline__ void ldsm4(unsigned* r, uint32_t addr) {
    asm volatile("ldmatrix.sync.aligned.m8n8.x4.shared.b16 {%0,%1,%2,%3}, [%4];"
                 : "=r"(r[0]), "=r"(r[1]), "=r"(r[2]), "=r"(r[3]) : "r"(addr));
}
__device__ __forceinline__ void ldsm4t(unsigned* r, uint32_t addr) {
    asm volatile("ldmatrix.sync.aligned.m8n8.x4.trans.shared.b16 {%0,%1,%2,%3}, [%4];"
                 : "=r"(r[0]), "=r"(r[1]), "=r"(r[2]), "=r"(r[3]) : "r"(addr));
}
__device__ __forceinline__ void mma_f16(float* d, const unsigned* a, const unsigned* b) {
    asm volatile(
        "mma.sync.aligned.m16n8k16.row.col.f32.f16.f16.f32 "
        "{%0,%1,%2,%3}, {%4,%5,%6,%7}, {%8,%9}, {%0,%1,%2,%3};\n"
        : "+f"(d[0]), "+f"(d[1]), "+f"(d[2]), "+f"(d[3])
        : "r"(a[0]), "r"(a[1]), "r"(a[2]), "r"(a[3]),
          "r"(b[0]), "r"(b[1]));
}
__device__ __forceinline__ unsigned pack_h2(float a, float b) {
    __half2 h = __floats2half2_rn(a, b);
    return *(unsigned*)&h;
}

// ---------------------------------------------------------------------------
// Pre-pass: fp32 -> fp16
// ---------------------------------------------------------------------------
__global__ void f2h_kernel(const float4* __restrict__ src, uint2* __restrict__ dst, int n4)
{
    int i = blockIdx.x * blockDim.x + threadIdx.x;
    if (i < n4) {
        float4 v = src[i];
        __half2 h0 = __floats2half2_rn(v.x, v.y);
        __half2 h1 = __floats2half2_rn(v.z, v.w);
        dst[i] = make_uint2(*(unsigned*)&h0, *(unsigned*)&h1);
    }
}

// ---------------------------------------------------------------------------
// fp16 tensor-core GEMM v3: C[M,N] = A[M,K]*B[N,K]^T, fp32 acc.
// CTA 128x256, BK=64, 256 threads = 8 warps (2x4), FAT warp tile 64x64,
// fragment double-buffering in registers (255-reg budget, 1 CTA/SM),
// 2-stage cp.async, one barrier per k-iteration.
// MODE 0: fp16 scatter into g_Qh/g_Kh/g_Vh; MODE 1: fp32 row-major C.
// ---------------------------------------------------------------------------
#define ROWH    72
#define TILEA_H (128 * ROWH)               // 9216 halves
#define TILEB_H (256 * ROWH)               // 18432 halves
#define STAGE_H (TILEA_H + TILEB_H)        // 27648 halves = 55296 B
#define GEMM_SMEM (2 * STAGE_H * 2)        // 110592 B

template <int MODE>
__global__ __launch_bounds__(256, 1)
void mm_f16(const __half* __restrict__ A, const __half* __restrict__ Bm,
            float* __restrict__ C, int Kdim, int Ndim)
{
    extern __shared__ __half smh[];
    const uint32_t smem_base = smem_u32(smh);

    const int m0 = blockIdx.y * 128;
    const int n0 = blockIdx.x * 256;
    const int t  = threadIdx.x;
    const int warp = t >> 5, lane = t & 31;
    const int wm = (warp >> 2) * 64;       // {0, 64}
    const int wn = (warp & 3) * 64;        // {0, 64, 128, 192}
    const int g = lane >> 2;
    const int q = lane & 3;

    float acc[4][8][4];
#pragma unroll
    for (int i = 0; i < 4; i++)
#pragma unroll
        for (int j = 0; j < 8; j++)
#pragma unroll
            for (int r = 0; r < 4; r++) acc[i][j][r] = 0.f;

    const uint32_t a_off = (uint32_t)((wm + (lane & 15)) * ROWH + (lane >> 4) * 8) * 2;
    const uint32_t b_off = (uint32_t)((wn + (lane & 7) + ((lane >> 4) << 3)) * ROWH
                                      + ((lane >> 3) & 1) * 8) * 2;

    const int KT = Kdim >> 6;              // 64-wide k-tiles

    auto prefetch = [&](int kt, int s) {
        __half* As = smh + s * STAGE_H;
        __half* Bs = As + TILEA_H;
        const int k0 = kt << 6;
#pragma unroll
        for (int u = 0; u < 4; u++) {      // A: 1024 chunks
            int idx = t + u * 256;
            int row = idx >> 3, c8 = (idx & 7) << 3;
            cp16(As + row * ROWH + c8, A + (size_t)(m0 + row) * Kdim + k0 + c8);
        }
#pragma unroll
        for (int u = 0; u < 8; u++) {      // B: 2048 chunks
            int idx = t + u * 256;
            int row = idx >> 3, c8 = (idx & 7) << 3;
            cp16(Bs + row * ROWH + c8, Bm + (size_t)(n0 + row) * Kdim + k0 + c8);
        }
    };

    prefetch(0, 0);
    cp_commit();

    unsigned af[2][4][4], bf[2][4][4];

    for (int kt = 0; kt < KT; kt++) {
        const int buf = kt & 1;
        cp_wait<0>();
        __syncthreads();

        if (kt + 1 < KT) {
            prefetch(kt + 1, buf ^ 1);
            cp_commit();
        }

        const uint32_t As_u = smem_base + (uint32_t)(buf * STAGE_H) * 2;
        const uint32_t Bs_u = As_u + TILEA_H * 2;

        // load fragment group 0
#pragma unroll
        for (int mi = 0; mi < 4; mi++)
            ldsm4(af[0][mi], As_u + a_off + (uint32_t)(mi * 16 * ROWH) * 2);
#pragma unroll
        for (int np = 0; np < 4; np++)
            ldsm4(bf[0][np], Bs_u + b_off + (uint32_t)(np * 16 * ROWH) * 2);

#pragma unroll
        for (int ks = 0; ks < 4; ks++) {
            const int cur = ks & 1;
            if (ks < 3) {                  // prefetch frag group ks+1
                const uint32_t kboff = (uint32_t)((ks + 1) * 16) * 2;
#pragma unroll
                for (int mi = 0; mi < 4; mi++)
                    ldsm4(af[cur ^ 1][mi],
                          As_u + a_off + kboff + (uint32_t)(mi * 16 * ROWH) * 2);
#pragma unroll
                for (int np = 0; np < 4; np++)
                    ldsm4(bf[cur ^ 1][np],
                          Bs_u + b_off + kboff + (uint32_t)(np * 16 * ROWH) * 2);
            }
#pragma unroll
            for (int mi = 0; mi < 4; mi++)
#pragma unroll
                for (int ni = 0; ni < 8; ni++)
                    mma_f16(acc[mi][ni], af[cur][mi], &bf[cur][ni >> 1][(ni & 1) * 2]);
        }
    }

#pragma unroll
    for (int mi = 0; mi < 4; mi++) {
        int mA = m0 + wm + mi * 16 + g;
#pragma unroll
        for (int ni = 0; ni < 8; ni++) {
            int n = n0 + wn + ni * 8 + 2 * q;
            if (MODE == 1) {
                float2 v0 = make_float2(acc[mi][ni][0], acc[mi][ni][1]);
                float2 v1 = make_float2(acc[mi][ni][2], acc[mi][ni][3]);
                *(float2*)(C + (size_t)mA * Ndim + n) = v0;
                *(float2*)(C + (size_t)(mA + 8) * Ndim + n) = v1;
            } else {
                int sel = n >> 10;
                int h   = (n >> 6) & (NH - 1);
                int hd  = n & (HDIM - 1);
                __half* dst = (sel == 0) ? g_Qh : (sel == 1) ? g_Kh : g_Vh;
                int b0r = mA >> 12, l0 = mA & (LL - 1);
                int b1r = (mA + 8) >> 12, l1 = (mA + 8) & (LL - 1);
                __half2 h0 = __floats2half2_rn(acc[mi][ni][0], acc[mi][ni][1]);
                __half2 h1 = __floats2half2_rn(acc[mi][ni][2], acc[mi][ni][3]);
                *(__half2*)(dst + ((size_t)(b0r * NH + h) * LL + l0) * HDIM + hd) = h0;
                *(__half2*)(dst + ((size_t)(b1r * NH + h) * LL + l1) * HDIM + hd) = h1;
            }
        }
    }
}

// ---------------------------------------------------------------------------
// Tensor-core block-local causal flash attention + fused RoPE.
// LOAD-BALANCED: warp w owns 16-row tiles t0=w and t1=15-w, giving every
// warp exactly 9 (16row x 32key) S/PV units instead of max 16.
// ---------------------------------------------------------------------------
#define AROW 72
#define ATILE (BSZ * AROW)                 // halves (18432)
#define ATTN_SMEM (3 * ATILE * 2)          // 110592 B

__global__ __launch_bounds__(256, 1)
void attn_tc()
{
    extern __shared__ __half sh[];
    __half* Qs = sh;
    __half* Ks = sh + ATILE;
    __half* Vs = sh + 2 * ATILE;
    const uint32_t Qs_u = smem_u32(Qs);
    const uint32_t Ks_u = Qs_u + ATILE * 2;
    const uint32_t Vs_u = Qs_u + 2 * ATILE * 2;

    const int cta = blockIdx.x;
    const int nb  = cta & (NBLK - 1);
    const int bh  = cta >> 4;
    const int b   = bh >> 4, h = bh & (NH - 1);
    const size_t rowbase = (size_t)bh * LL + (size_t)nb * BSZ;

    const int t = threadIdx.x;
    const int warp = t >> 5, lane = t & 31;
    const int g  = lane >> 2;
    const int q2 = (lane & 3) * 2;

    {
        const __half* Qg = g_Qh + rowbase * HDIM;
        const __half* Kg = g_Kh + rowbase * HDIM;
        const __half* Vg = g_Vh + rowbase * HDIM;
        for (int idx = t; idx < BSZ * HDIM / 8; idx += 256) {
            int row = idx >> 3, c8 = (idx & 7) << 3;
            cp16(Qs + row * AROW + c8, Qg + row * HDIM + c8);
            cp16(Ks + row * AROW + c8, Kg + row * HDIM + c8);
            cp16(Vs + row * AROW + c8, Vg + row * HDIM + c8);
        }
        cp_commit(); cp_wait<0>();
        __syncthreads();
    }

    // RoPE in-smem: read full row to regs first, then write (no overlap).
    {
        const int row = t;
        const float pos = (float)(nb * BSZ + row);
        float cs[32], sn[32];
#pragma unroll
        for (int i = 0; i < 32; i++) {
            float ang = pos * __expf(-(float)i * (9.210340371976184f / 32.0f));
            __sincosf(ang, &sn[i], &cs[i]);
        }
#pragma unroll
        for (int pass = 0; pass < 2; pass++) {
            __half* p = (pass == 0 ? Qs : Ks) + row * AROW;
            float xv[64];
#pragma unroll
            for (int d = 0; d < 32; d++) {
                __half2 v = ((__half2*)p)[d];
                xv[2 * d]     = __half2float(v.x);
                xv[2 * d + 1] = __half2float(v.y);
            }
#pragma unroll
            for (int i = 0; i < 32; i += 2) {
                *(__half2*)(p + i) = __floats2half2_rn(
                    xv[2 * i]     * cs[i]     - xv[2 * i + 1] * sn[i],
                    xv[2 * i + 2] * cs[i + 1] - xv[2 * i + 3] * sn[i + 1]);
                *(__half2*)(p + 32 + i) = __floats2half2_rn(
                    xv[2 * i + 1] * cs[i]     + xv[2 * i]     * sn[i],
                    xv[2 * i + 3] * cs[i + 1] + xv[2 * i + 2] * sn[i + 1]);
            }
        }
        __syncthreads();
    }

    // Tiles owned by this warp: t0 (small) and t1 (large).
    const int tt[2] = { warp, 15 - warp };
    const int Ct[2] = { warp / 2 + 1, (15 - warp) / 2 + 1 };
    const int Cmax = Ct[1];                // t1 >= 8 so Ct[1] >= Ct[0]

    // Q fragments per tile (rows 16*tt[mt] .. +15)
    unsigned qf[2][4][4];
#pragma unroll
    for (int mt = 0; mt < 2; mt++)
#pragma unroll
        for (int ks = 0; ks < 4; ks++)
            ldsm4(qf[mt][ks], Qs_u + (uint32_t)(((tt[mt] * 16 + (lane & 15)) * AROW
                                                 + ks * 16 + (lane >> 4) * 8) * 2));

    float o[2][8][4];
#pragma unroll
    for (int mt = 0; mt < 2; mt++)
#pragma unroll
        for (int nd = 0; nd < 8; nd++)
#pragma unroll
            for (int e = 0; e < 4; e++) o[mt][nd][e] = 0.f;

    float mrow[2][2] = {{-1e30f, -1e30f}, {-1e30f, -1e30f}};
    float lrow[2][2] = {{0.f, 0.f}, {0.f, 0.f}};

    for (int c = 0; c < Cmax; c++) {
        // ---- K fragments for this 32-key chunk (shared by both tiles) ----
        unsigned bk[4][2][4];              // [ks][half16][4]
#pragma unroll
        for (int ks = 0; ks < 4; ks++) {
            uint32_t base = Ks_u + (uint32_t)(((c * 32 + (lane & 7) + ((lane >> 4) << 3)) * AROW
                                               + ks * 16 + ((lane >> 3) & 1) * 8) * 2);
            ldsm4(bk[ks][0], base);
            ldsm4(bk[ks][1], base + (uint32_t)(16 * AROW * 2));
        }

        float s[2][4][4];
#pragma unroll
        for (int mt = 0; mt < 2; mt++) {
            if (c >= Ct[mt]) continue;     // tile inactive for this chunk
#pragma unroll
            for (int nt = 0; nt < 4; nt++)
#pragma unroll
                for (int e = 0; e < 4; e++) s[mt][nt][e] = 0.f;
#pragma unroll
            for (int ks = 0; ks < 4; ks++) {
                mma_f16(s[mt][0], qf[mt][ks], &bk[ks][0][0]);
                mma_f16(s[mt][1], qf[mt][ks], &bk[ks][0][2]);
                mma_f16(s[mt][2], qf[mt][ks], &bk[ks][1][0]);
                mma_f16(s[mt][3], qf[mt][ks], &bk[ks][1][2]);
            }

            // scale + causal mask (global coords) + online softmax
#pragma unroll
            for (int nt = 0; nt < 4; nt++)
#pragma unroll
                for (int e = 0; e < 4; e++) s[mt][nt][e] *= 0.125f;

            if (c == Ct[mt] - 1) {
                const int rA = tt[mt] * 16 + g, rB = rA + 8;
#pragma unroll
                for (int nt = 0; nt < 4; nt++) {
                    int colg = 32 * c + 8 * nt + q2;
                    if (colg     > rA) s[mt][nt][0] = -1e30f;
                    if (colg + 1 > rA) s[mt][nt][1] = -1e30f;
                    if (colg     > rB) s[mt][nt][2] = -1e30f;
                    if (colg + 1 > rB) s[mt][nt][3] = -1e30f;
                }
            }

            float mxA = -1e30f, mxB = -1e30f;
#pragma unroll
            for (int nt = 0; nt < 4; nt++) {
                mxA = fmaxf(mxA, fmaxf(s[mt][nt][0], s[mt][nt][1]));
                mxB = fmaxf(mxB, fmaxf(s[mt][nt][2], s[mt][nt][3]));
            }
            mxA = fmaxf(mxA, __shfl_xor_sync(0xFFFFFFFFu, mxA, 1));
            mxA = fmaxf(mxA, __shfl_xor_sync(0xFFFFFFFFu, mxA, 2));
            mxB = fmaxf(mxB, __shfl_xor_sync(0xFFFFFFFFu, mxB, 1));
            mxB = fmaxf(mxB, __shfl_xor_sync(0xFFFFFFFFu, mxB, 2));

            float newA = fmaxf(mrow[mt][0], mxA);
            float newB = fmaxf(mrow[mt][1], mxB);
            float fA = __expf(mrow[mt][0] - newA);
            float fB = __expf(mrow[mt][1] - newB);
            mrow[mt][0] = newA; mrow[mt][1] = newB;

            float sumA = 0.f, sumB = 0.f;
#pragma unroll
            for (int nt = 0; nt < 4; nt++) {
                s[mt][nt][0] = __expf(s[mt][nt][0] - newA);
                s[mt][nt][1] = __expf(s[mt][nt][1] - newA);
                s[mt][nt][2] = __expf(s[mt][nt][2] - newB);
                s[mt][nt][3] = __expf(s[mt][nt][3] - newB);
                sumA += s[mt][nt][0] + s[mt][nt][1];
                sumB += s[mt][nt][2] + s[mt][nt][3];
            }
            sumA += __shfl_xor_sync(0xFFFFFFFFu, sumA, 1);
            sumA += __shfl_xor_sync(0xFFFFFFFFu, sumA, 2);
            sumB += __shfl_xor_sync(0xFFFFFFFFu, sumB, 1);
            sumB += __shfl_xor_sync(0xFFFFFFFFu, sumB, 2);
            lrow[mt][0] = lrow[mt][0] * fA + sumA;
            lrow[mt][1] = lrow[mt][1] * fB + sumB;

#pragma unroll
            for (int nd = 0; nd < 8; nd++) {
                o[mt][nd][0] *= fA; o[mt][nd][1] *= fA;
                o[mt][nd][2] *= fB; o[mt][nd][3] *= fB;
            }
        }

        // ---- PV (V fragments shared by both tiles) ----
#pragma unroll
        for (int pt = 0; pt < 2; pt++) {
            unsigned vb[4][4];
#pragma unroll
            for (int nd16 = 0; nd16 < 4; nd16++) {
                uint32_t addr = Vs_u + (uint32_t)(((c * 32 + pt * 16 + (lane & 7)
                                                   + (((lane >> 3) & 1) << 3)) * AROW
                                                  + nd16 * 16 + (lane >> 4) * 8) * 2);
                ldsm4t(vb[nd16], addr);
            }
#pragma unroll
            for (int mt = 0; mt < 2; mt++) {
                if (c >= Ct[mt]) continue;
                unsigned pa[4];
                pa[0] = pack_h2(s[mt][2 * pt][0],     s[mt][2 * pt][1]);
                pa[1] = pack_h2(s[mt][2 * pt][2],     s[mt][2 * pt][3]);
                pa[2] = pack_h2(s[mt][2 * pt + 1][0], s[mt][2 * pt + 1][1]);
                pa[3] = pack_h2(s[mt][2 * pt + 1][2], s[mt][2 * pt + 1][3]);
#pragma unroll
                for (int nd16 = 0; nd16 < 4; nd16++) {
                    mma_f16(o[mt][2 * nd16],     pa, &vb[nd16][0]);
                    mma_f16(o[mt][2 * nd16 + 1], pa, &vb[nd16][2]);
                }
            }
        }
    }

    // ---- normalize + store O (fp16, [B,L,D] layout) ----
#pragma unroll
    for (int mt = 0; mt < 2; mt++) {
        float iA = 1.f / lrow[mt][0];
        float iB = 1.f / lrow[mt][1];
        const int rA = tt[mt] * 16 + g;
        size_t baseA = ((size_t)(b * LL) + nb * BSZ + rA) * DD + h * HDIM;
        size_t baseB = baseA + (size_t)8 * DD;
#pragma unroll
        for (int nd = 0; nd < 8; nd++) {
            *(__half2*)(g_Oh + baseA + 8 * nd + q2) =
                __floats2half2_rn(o[mt][nd][0] * iA, o[mt][nd][1] * iA);
            *(__half2*)(g_Oh + baseB + 8 * nd + q2) =
                __floats2half2_rn(o[mt][nd][2] * iB, o[mt][nd][3] * iB);
        }
    }
}

// ---------------------------------------------------------------------------
extern "C" void kernel_launch(void* const* d_in, const int* in_sizes, int n_in,
                              void* d_out, int out_size)
{
    const float* x    = (const float*)d_in[0];
    const float* Wqkv = (const float*)d_in[1];
    const float* Wout = (const float*)d_in[2];
    float* out = (float*)d_out;

    void *Oh = nullptr, *Xh = nullptr, *Wqh = nullptr, *Woh = nullptr;
    cudaGetSymbolAddress(&Oh, g_Oh);
    cudaGetSymbolAddress(&Xh, g_Xh);
    cudaGetSymbolAddress(&Wqh, g_Wqkvh);
    cudaGetSymbolAddress(&Woh, g_Wouth);

    cudaFuncSetAttribute(mm_f16<0>, cudaFuncAttributeMaxDynamicSharedMemorySize, GEMM_SMEM);
    cudaFuncSetAttribute(mm_f16<1>, cudaFuncAttributeMaxDynamicSharedMemorySize, GEMM_SMEM);
    cudaFuncSetAttribute(attn_tc, cudaFuncAttributeMaxDynamicSharedMemorySize, ATTN_SMEM);

    // 0) fp32 -> fp16 conversion of x, Wqkv, Wout
    {
        int n4x = MR * DD / 4, n4q = 3 * DD * DD / 4, n4o = DD * DD / 4;
        f2h_kernel<<<(n4x + 255) / 256, 256>>>((const float4*)x, (uint2*)Xh, n4x);
        f2h_kernel<<<(n4q + 255) / 256, 256>>>((const float4*)Wqkv, (uint2*)Wqh, n4q);
        f2h_kernel<<<(n4o + 255) / 256, 256>>>((const float4*)Wout, (uint2*)Woh, n4o);
    }

    // 1) QKV projection (fp16 tensor cores) -> fp16 Q/K/V in [B,H,L,HD]
    mm_f16<0><<<dim3(3 * DD / 256, MR / 128), 256, GEMM_SMEM>>>(
        (const __half*)Xh, (const __half*)Wqh, nullptr, DD, 3 * DD);

    // 2) Fused RoPE + balanced tensor-core flash attention -> g_Oh fp16 [B,L,D]
    attn_tc<<<BB * NH * NBLK, 256, ATTN_SMEM>>>();

    // 3) Output projection (fp16 tensor cores) -> fp32 out
    mm_f16<1><<<dim3(DD / 256, MR / 128), 256, GEMM_SMEM>>>(
        (const __half*)Oh, (const __half*)Woh, out, DD, DD);
}

// round 11
// speedup vs baseline: 1.0977x; 1.0977x over previous
#include <cuda_runtime.h>
#include <cuda_fp16.h>
#include <math.h>
#include <cstdint>

#define BB   2
#define LL   4096
#define DD   1024
#define NH   16
#define HDIM 64
#define BSZ  256
#define NBLK (LL / BSZ)     // 16
#define MR   (BB * LL)      // 8192

// Scratch (allocation-free, __device__ globals) — all fp16
__device__ __half g_Qh[BB * NH * LL * HDIM];
__device__ __half g_Kh[BB * NH * LL * HDIM];
__device__ __half g_Vh[BB * NH * LL * HDIM];
__device__ __half g_Oh[MR * DD];
__device__ __half g_Xh[MR * DD];
__device__ __half g_Wqkvh[3 * DD * DD];
__device__ __half g_Wouth[DD * DD];

// ---------------------------------------------------------------------------
// helpers
// ---------------------------------------------------------------------------
__device__ __forceinline__ uint32_t smem_u32(const void* p) {
    uint32_t a;
    asm("{ .reg .u64 t; cvta.to.shared.u64 t, %1; cvt.u32.u64 %0, t; }" : "=r"(a) : "l"(p));
    return a;
}
__device__ __forceinline__ void cp16(void* smem_dst, const void* gmem_src) {
    unsigned s = (unsigned)__cvta_generic_to_shared(smem_dst);
    asm volatile("cp.async.cg.shared.global [%0], [%1], 16;\n" :: "r"(s), "l"(gmem_src));
}
__device__ __forceinline__ void cp_commit() { asm volatile("cp.async.commit_group;\n"); }
template <int N>
__device__ __forceinline__ void cp_wait() { asm volatile("cp.async.wait_group %0;\n" :: "n"(N)); }

__device__ __forceinline__ void ldsm4(unsigned* r, uint32_t addr) {
    asm volatile("ldmatrix.sync.aligned.m8n8.x4.shared.b16 {%0,%1,%2,%3}, [%4];"
                 : "=r"(r[0]), "=r"(r[1]), "=r"(r[2]), "=r"(r[3]) : "r"(addr));
}
__device__ __forceinline__ void ldsm4t(unsigned* r, uint32_t addr) {
    asm volatile("ldmatrix.sync.aligned.m8n8.x4.trans.shared.b16 {%0,%1,%2,%3}, [%4];"
                 : "=r"(r[0]), "=r"(r[1]), "=r"(r[2]), "=r"(r[3]) : "r"(addr));
}
__device__ __forceinline__ void mma_f16(float* d, const unsigned* a, const unsigned* b) {
    asm volatile(
        "mma.sync.aligned.m16n8k16.row.col.f32.f16.f16.f32 "
        "{%0,%1,%2,%3}, {%4,%5,%6,%7}, {%8,%9}, {%0,%1,%2,%3};\n"
        : "+f"(d[0]), "+f"(d[1]), "+f"(d[2]), "+f"(d[3])
        : "r"(a[0]), "r"(a[1]), "r"(a[2]), "r"(a[3]),
          "r"(b[0]), "r"(b[1]));
}
__device__ __forceinline__ unsigned pack_h2(float a, float b) {
    __half2 h = __floats2half2_rn(a, b);
    return *(unsigned*)&h;
}

// ---------------------------------------------------------------------------
// Pre-pass: fp32 -> fp16
// ---------------------------------------------------------------------------
__global__ void f2h_kernel(const float4* __restrict__ src, uint2* __restrict__ dst, int n4)
{
    int i = blockIdx.x * blockDim.x + threadIdx.x;
    if (i < n4) {
        float4 v = src[i];
        __half2 h0 = __floats2half2_rn(v.x, v.y);
        __half2 h1 = __floats2half2_rn(v.z, v.w);
        dst[i] = make_uint2(*(unsigned*)&h0, *(unsigned*)&h1);
    }
}

// ---------------------------------------------------------------------------
// fp16 tensor-core GEMM v4: C[M,N] = A[M,K]*B[N,K]^T, fp32 acc.
// CTA 128x128, BK=64, 8 warps (2x4), warp 64x32, ldmatrix.x4,
// THREE-stage cp.async (wait<1> at top -> two compute phases of load slack),
// one barrier per k-iteration. 110.6 KB smem, 128 regs -> 2 CTAs/SM.
// MODE 0: fp16 scatter into g_Qh/g_Kh/g_Vh; MODE 1: fp32 row-major C.
// ---------------------------------------------------------------------------
#define ROWH   72
#define TILE_H (128 * ROWH)                // 9216 halves per operand tile
#define STAGE_H (2 * TILE_H)               // 18432 halves = 36864 B
#define NSTG   3
#define GEMM_SMEM (NSTG * STAGE_H * 2)     // 110592 B

template <int MODE>
__global__ __launch_bounds__(256, 2)
void mm_f16(const __half* __restrict__ A, const __half* __restrict__ Bm,
            float* __restrict__ C, int Kdim, int Ndim)
{
    extern __shared__ __half smh[];
    const uint32_t smem_base = smem_u32(smh);

    const int m0 = blockIdx.y * 128;
    const int n0 = blockIdx.x * 128;
    const int t  = threadIdx.x;
    const int warp = t >> 5, lane = t & 31;
    const int wm = (warp >> 2) * 64;
    const int wn = (warp & 3) * 32;
    const int g = lane >> 2;
    const int q = lane & 3;

    float acc[4][4][4];
#pragma unroll
    for (int i = 0; i < 4; i++)
#pragma unroll
        for (int j = 0; j < 4; j++)
#pragma unroll
            for (int r = 0; r < 4; r++) acc[i][j][r] = 0.f;

    const uint32_t a_off = (uint32_t)((wm + (lane & 15)) * ROWH + (lane >> 4) * 8) * 2;
    const uint32_t b_off = (uint32_t)((wn + (lane & 7) + ((lane >> 4) << 3)) * ROWH
                                      + ((lane >> 3) & 1) * 8) * 2;

    const int KT = Kdim >> 6;              // 64-wide k-tiles

    auto prefetch = [&](int kt, int s) {
        __half* As = smh + s * STAGE_H;
        __half* Bs = As + TILE_H;
        const int k0 = kt << 6;
#pragma unroll
        for (int u = 0; u < 4; u++) {
            int idx = t + u * 256;
            int row = idx >> 3, c8 = (idx & 7) << 3;
            cp16(As + row * ROWH + c8, A + (size_t)(m0 + row) * Kdim + k0 + c8);
        }
#pragma unroll
        for (int u = 0; u < 4; u++) {
            int idx = t + u * 256;
            int row = idx >> 3, c8 = (idx & 7) << 3;
            cp16(Bs + row * ROWH + c8, Bm + (size_t)(n0 + row) * Kdim + k0 + c8);
        }
    };

    prefetch(0, 0); cp_commit();
    prefetch(1, 1); cp_commit();

    int sbuf = 0;                          // stage holding tile kt
    for (int kt = 0; kt < KT; kt++) {
        if (kt + 1 < KT) cp_wait<1>();     // tile kt resident (kt+1 may be in flight)
        else             cp_wait<0>();
        __syncthreads();                   // stage (kt-1)%3 fully consumed by all warps

        if (kt + 2 < KT) {
            int s2 = sbuf + 2; if (s2 >= NSTG) s2 -= NSTG;   // == (kt-1)%3, just freed
            prefetch(kt + 2, s2);
            cp_commit();
        }

        const uint32_t As_u = smem_base + (uint32_t)(sbuf * STAGE_H) * 2;
        const uint32_t Bs_u = As_u + TILE_H * 2;

#pragma unroll
        for (int ks = 0; ks < 4; ks++) {
            unsigned af[4][4], bf[2][4];
            const uint32_t kboff = (uint32_t)(ks * 16) * 2;
#pragma unroll
            for (int mi = 0; mi < 4; mi++)
                ldsm4(af[mi], As_u + a_off + kboff + (uint32_t)(mi * 16 * ROWH) * 2);
#pragma unroll
            for (int np = 0; np < 2; np++)
                ldsm4(bf[np], Bs_u + b_off + kboff + (uint32_t)(np * 16 * ROWH) * 2);
#pragma unroll
            for (int mi = 0; mi < 4; mi++)
#pragma unroll
                for (int ni = 0; ni < 4; ni++)
                    mma_f16(acc[mi][ni], af[mi], &bf[ni >> 1][(ni & 1) * 2]);
        }
        sbuf++; if (sbuf >= NSTG) sbuf = 0;
    }

#pragma unroll
    for (int mi = 0; mi < 4; mi++) {
        int mA = m0 + wm + mi * 16 + g;
#pragma unroll
        for (int ni = 0; ni < 4; ni++) {
            int n = n0 + wn + ni * 8 + 2 * q;
            if (MODE == 1) {
                float2 v0 = make_float2(acc[mi][ni][0], acc[mi][ni][1]);
                float2 v1 = make_float2(acc[mi][ni][2], acc[mi][ni][3]);
                *(float2*)(C + (size_t)mA * Ndim + n) = v0;
                *(float2*)(C + (size_t)(mA + 8) * Ndim + n) = v1;
            } else {
                int sel = n >> 10;
                int h   = (n >> 6) & (NH - 1);
                int hd  = n & (HDIM - 1);
                __half* dst = (sel == 0) ? g_Qh : (sel == 1) ? g_Kh : g_Vh;
                int b0r = mA >> 12, l0 = mA & (LL - 1);
                int b1r = (mA + 8) >> 12, l1 = (mA + 8) & (LL - 1);
                __half2 h0 = __floats2half2_rn(acc[mi][ni][0], acc[mi][ni][1]);
                __half2 h1 = __floats2half2_rn(acc[mi][ni][2], acc[mi][ni][3]);
                *(__half2*)(dst + ((size_t)(b0r * NH + h) * LL + l0) * HDIM + hd) = h0;
                *(__half2*)(dst + ((size_t)(b1r * NH + h) * LL + l1) * HDIM + hd) = h1;
            }
        }
    }
}

// ---------------------------------------------------------------------------
// Tensor-core block-local causal flash attention + fused RoPE.
// LOAD-BALANCED: warp w owns 16-row tiles t0=w and t1=15-w (9 chunks each).
// ---------------------------------------------------------------------------
#define AROW 72
#define ATILE (BSZ * AROW)                 // halves (18432)
#define ATTN_SMEM (3 * ATILE * 2)          // 110592 B

__global__ __launch_bounds__(256, 1)
void attn_tc()
{
    extern __shared__ __half sh[];
    __half* Qs = sh;
    __half* Ks = sh + ATILE;
    __half* Vs = sh + 2 * ATILE;
    const uint32_t Qs_u = smem_u32(Qs);
    const uint32_t Ks_u = Qs_u + ATILE * 2;
    const uint32_t Vs_u = Qs_u + 2 * ATILE * 2;

    const int cta = blockIdx.x;
    const int nb  = cta & (NBLK - 1);
    const int bh  = cta >> 4;
    const int b   = bh >> 4, h = bh & (NH - 1);
    const size_t rowbase = (size_t)bh * LL + (size_t)nb * BSZ;

    const int t = threadIdx.x;
    const int warp = t >> 5, lane = t & 31;
    const int g  = lane >> 2;
    const int q2 = (lane & 3) * 2;

    {
        const __half* Qg = g_Qh + rowbase * HDIM;
        const __half* Kg = g_Kh + rowbase * HDIM;
        const __half* Vg = g_Vh + rowbase * HDIM;
        for (int idx = t; idx < BSZ * HDIM / 8; idx += 256) {
            int row = idx >> 3, c8 = (idx & 7) << 3;
            cp16(Qs + row * AROW + c8, Qg + row * HDIM + c8);
            cp16(Ks + row * AROW + c8, Kg + row * HDIM + c8);
            cp16(Vs + row * AROW + c8, Vg + row * HDIM + c8);
        }
        cp_commit(); cp_wait<0>();
        __syncthreads();
    }

    // RoPE in-smem: read full row to regs first, then write (no overlap).
    {
        const int row = t;
        const float pos = (float)(nb * BSZ + row);
        float cs[32], sn[32];
#pragma unroll
        for (int i = 0; i < 32; i++) {
            float ang = pos * __expf(-(float)i * (9.210340371976184f / 32.0f));
            __sincosf(ang, &sn[i], &cs[i]);
        }
#pragma unroll
        for (int pass = 0; pass < 2; pass++) {
            __half* p = (pass == 0 ? Qs : Ks) + row * AROW;
            float xv[64];
#pragma unroll
            for (int d = 0; d < 32; d++) {
                __half2 v = ((__half2*)p)[d];
                xv[2 * d]     = __half2float(v.x);
                xv[2 * d + 1] = __half2float(v.y);
            }
#pragma unroll
            for (int i = 0; i < 32; i += 2) {
                *(__half2*)(p + i) = __floats2half2_rn(
                    xv[2 * i]     * cs[i]     - xv[2 * i + 1] * sn[i],
                    xv[2 * i + 2] * cs[i + 1] - xv[2 * i + 3] * sn[i + 1]);
                *(__half2*)(p + 32 + i) = __floats2half2_rn(
                    xv[2 * i + 1] * cs[i]     + xv[2 * i]     * sn[i],
                    xv[2 * i + 3] * cs[i + 1] + xv[2 * i + 2] * sn[i + 1]);
            }
        }
        __syncthreads();
    }

    const int tt[2] = { warp, 15 - warp };
    const int Ct[2] = { warp / 2 + 1, (15 - warp) / 2 + 1 };
    const int Cmax = Ct[1];

    unsigned qf[2][4][4];
#pragma unroll
    for (int mt = 0; mt < 2; mt++)
#pragma unroll
        for (int ks = 0; ks < 4; ks++)
            ldsm4(qf[mt][ks], Qs_u + (uint32_t)(((tt[mt] * 16 + (lane & 15)) * AROW
                                                 + ks * 16 + (lane >> 4) * 8) * 2));

    float o[2][8][4];
#pragma unroll
    for (int mt = 0; mt < 2; mt++)
#pragma unroll
        for (int nd = 0; nd < 8; nd++)
#pragma unroll
            for (int e = 0; e < 4; e++) o[mt][nd][e] = 0.f;

    float mrow[2][2] = {{-1e30f, -1e30f}, {-1e30f, -1e30f}};
    float lrow[2][2] = {{0.f, 0.f}, {0.f, 0.f}};

    for (int c = 0; c < Cmax; c++) {
        unsigned bk[4][2][4];
#pragma unroll
        for (int ks = 0; ks < 4; ks++) {
            uint32_t base = Ks_u + (uint32_t)(((c * 32 + (lane & 7) + ((lane >> 4) << 3)) * AROW
                                               + ks * 16 + ((lane >> 3) & 1) * 8) * 2);
            ldsm4(bk[ks][0], base);
            ldsm4(bk[ks][1], base + (uint32_t)(16 * AROW * 2));
        }

        float s[2][4][4];
#pragma unroll
        for (int mt = 0; mt < 2; mt++) {
            if (c >= Ct[mt]) continue;
#pragma unroll
            for (int nt = 0; nt < 4; nt++)
#pragma unroll
                for (int e = 0; e < 4; e++) s[mt][nt][e] = 0.f;
#pragma unroll
            for (int ks = 0; ks < 4; ks++) {
                mma_f16(s[mt][0], qf[mt][ks], &bk[ks][0][0]);
                mma_f16(s[mt][1], qf[mt][ks], &bk[ks][0][2]);
                mma_f16(s[mt][2], qf[mt][ks], &bk[ks][1][0]);
                mma_f16(s[mt][3], qf[mt][ks], &bk[ks][1][2]);
            }

#pragma unroll
            for (int nt = 0; nt < 4; nt++)
#pragma unroll
                for (int e = 0; e < 4; e++) s[mt][nt][e] *= 0.125f;

            if (c == Ct[mt] - 1) {
                const int rA = tt[mt] * 16 + g, rB = rA + 8;
#pragma unroll
                for (int nt = 0; nt < 4; nt++) {
                    int colg = 32 * c + 8 * nt + q2;
                    if (colg     > rA) s[mt][nt][0] = -1e30f;
                    if (colg + 1 > rA) s[mt][nt][1] = -1e30f;
                    if (colg     > rB) s[mt][nt][2] = -1e30f;
                    if (colg + 1 > rB) s[mt][nt][3] = -1e30f;
                }
            }

            float mxA = -1e30f, mxB = -1e30f;
#pragma unroll
            for (int nt = 0; nt < 4; nt++) {
                mxA = fmaxf(mxA, fmaxf(s[mt][nt][0], s[mt][nt][1]));
                mxB = fmaxf(mxB, fmaxf(s[mt][nt][2], s[mt][nt][3]));
            }
            mxA = fmaxf(mxA, __shfl_xor_sync(0xFFFFFFFFu, mxA, 1));
            mxA = fmaxf(mxA, __shfl_xor_sync(0xFFFFFFFFu, mxA, 2));
            mxB = fmaxf(mxB, __shfl_xor_sync(0xFFFFFFFFu, mxB, 1));
            mxB = fmaxf(mxB, __shfl_xor_sync(0xFFFFFFFFu, mxB, 2));

            float newA = fmaxf(mrow[mt][0], mxA);
            float newB = fmaxf(mrow[mt][1], mxB);
            float fA = __expf(mrow[mt][0] - newA);
            float fB = __expf(mrow[mt][1] - newB);
            mrow[mt][0] = newA; mrow[mt][1] = newB;

            float sumA = 0.f, sumB = 0.f;
#pragma unroll
            for (int nt = 0; nt < 4; nt++) {
                s[mt][nt][0] = __expf(s[mt][nt][0] - newA);
                s[mt][nt][1] = __expf(s[mt][nt][1] - newA);
                s[mt][nt][2] = __expf(s[mt][nt][2] - newB);
                s[mt][nt][3] = __expf(s[mt][nt][3] - newB);
                sumA += s[mt][nt][0] + s[mt][nt][1];
                sumB += s[mt][nt][2] + s[mt][nt][3];
            }
            sumA += __shfl_xor_sync(0xFFFFFFFFu, sumA, 1);
            sumA += __shfl_xor_sync(0xFFFFFFFFu, sumA, 2);
            sumB += __shfl_xor_sync(0xFFFFFFFFu, sumB, 1);
            sumB += __shfl_xor_sync(0xFFFFFFFFu, sumB, 2);
            lrow[mt][0] = lrow[mt][0] * fA + sumA;
            lrow[mt][1] = lrow[mt][1] * fB + sumB;

#pragma unroll
            for (int nd = 0; nd < 8; nd++) {
                o[mt][nd][0] *= fA; o[mt][nd][1] *= fA;
                o[mt][nd][2] *= fB; o[mt][nd][3] *= fB;
            }
        }

#pragma unroll
        for (int pt = 0; pt < 2; pt++) {
            unsigned vb[4][4];
#pragma unroll
            for (int nd16 = 0; nd16 < 4; nd16++) {
                uint32_t addr = Vs_u + (uint32_t)(((c * 32 + pt * 16 + (lane & 7)
                                                   + (((lane >> 3) & 1) << 3)) * AROW
                                                  + nd16 * 16 + (lane >> 4) * 8) * 2);
                ldsm4t(vb[nd16], addr);
            }
#pragma unroll
            for (int mt = 0; mt < 2; mt++) {
                if (c >= Ct[mt]) continue;
                unsigned pa[4];
                pa[0] = pack_h2(s[mt][2 * pt][0],     s[mt][2 * pt][1]);
                pa[1] = pack_h2(s[mt][2 * pt][2],     s[mt][2 * pt][3]);
                pa[2] = pack_h2(s[mt][2 * pt + 1][0], s[mt][2 * pt + 1][1]);
                pa[3] = pack_h2(s[mt][2 * pt + 1][2], s[mt][2 * pt + 1][3]);
#pragma unroll
                for (int nd16 = 0; nd16 < 4; nd16++) {
                    mma_f16(o[mt][2 * nd16],     pa, &vb[nd16][0]);
                    mma_f16(o[mt][2 * nd16 + 1], pa, &vb[nd16][2]);
                }
            }
        }
    }

#pragma unroll
    for (int mt = 0; mt < 2; mt++) {
        float iA = 1.f / lrow[mt][0];
        float iB = 1.f / lrow[mt][1];
        const int rA = tt[mt] * 16 + g;
        size_t baseA = ((size_t)(b * LL) + nb * BSZ + rA) * DD + h * HDIM;
        size_t baseB = baseA + (size_t)8 * DD;
#pragma unroll
        for (int nd = 0; nd < 8; nd++) {
            *(__half2*)(g_Oh + baseA + 8 * nd + q2) =
                __floats2half2_rn(o[mt][nd][0] * iA, o[mt][nd][1] * iA);
            *(__half2*)(g_Oh + baseB + 8 * nd + q2) =
                __floats2half2_rn(o[mt][nd][2] * iB, o[mt][nd][3] * iB);
        }
    }
}

// ---------------------------------------------------------------------------
extern "C" void kernel_launch(void* const* d_in, const int* in_sizes, int n_in,
                              void* d_out, int out_size)
{
    const float* x    = (const float*)d_in[0];
    const float* Wqkv = (const float*)d_in[1];
    const float* Wout = (const float*)d_in[2];
    float* out = (float*)d_out;

    void *Oh = nullptr, *Xh = nullptr, *Wqh = nullptr, *Woh = nullptr;
    cudaGetSymbolAddress(&Oh, g_Oh);
    cudaGetSymbolAddress(&Xh, g_Xh);
    cudaGetSymbolAddress(&Wqh, g_Wqkvh);
    cudaGetSymbolAddress(&Woh, g_Wouth);

    cudaFuncSetAttribute(mm_f16<0>, cudaFuncAttributeMaxDynamicSharedMemorySize, GEMM_SMEM);
    cudaFuncSetAttribute(mm_f16<1>, cudaFuncAttributeMaxDynamicSharedMemorySize, GEMM_SMEM);
    cudaFuncSetAttribute(attn_tc, cudaFuncAttributeMaxDynamicSharedMemorySize, ATTN_SMEM);

    // 0) fp32 -> fp16 conversion of x, Wqkv, Wout
    {
        int n4x = MR * DD / 4, n4q = 3 * DD * DD / 4, n4o = DD * DD / 4;
        f2h_kernel<<<(n4x + 255) / 256, 256>>>((const float4*)x, (uint2*)Xh, n4x);
        f2h_kernel<<<(n4q + 255) / 256, 256>>>((const float4*)Wqkv, (uint2*)Wqh, n4q);
        f2h_kernel<<<(n4o + 255) / 256, 256>>>((const float4*)Wout, (uint2*)Woh, n4o);
    }

    // 1) QKV projection (fp16 tensor cores) -> fp16 Q/K/V in [B,H,L,HD]
    mm_f16<0><<<dim3(3 * DD / 128, MR / 128), 256, GEMM_SMEM>>>(
        (const __half*)Xh, (const __half*)Wqh, nullptr, DD, 3 * DD);

    // 2) Fused RoPE + balanced tensor-core flash attention -> g_Oh fp16 [B,L,D]
    attn_tc<<<BB * NH * NBLK, 256, ATTN_SMEM>>>();

    // 3) Output projection (fp16 tensor cores) -> fp32 out
    mm_f16<1><<<dim3(DD / 128, MR / 128), 256, GEMM_SMEM>>>(
        (const __half*)Oh, (const __half*)Woh, out, DD, DD);
}

// round 12
// speedup vs baseline: 1.1196x; 1.0199x over previous
#include <cuda_runtime.h>
#include <cuda_fp16.h>
#include <math.h>
#include <cstdint>

#define BB   2
#define LL   4096
#define DD   1024
#define NH   16
#define HDIM 64
#define BSZ  256
#define NBLK (LL / BSZ)     // 16
#define MR   (BB * LL)      // 8192

// Scratch (allocation-free, __device__ globals) — all fp16
__device__ __half g_Qh[BB * NH * LL * HDIM];
__device__ __half g_Kh[BB * NH * LL * HDIM];
__device__ __half g_Vh[BB * NH * LL * HDIM];
__device__ __half g_Oh[MR * DD];
__device__ __half g_Xh[MR * DD];
__device__ __half g_Wqkvh[3 * DD * DD];
__device__ __half g_Wouth[DD * DD];

// ---------------------------------------------------------------------------
// helpers
// ---------------------------------------------------------------------------
__device__ __forceinline__ uint32_t smem_u32(const void* p) {
    uint32_t a;
    asm("{ .reg .u64 t; cvta.to.shared.u64 t, %1; cvt.u32.u64 %0, t; }" : "=r"(a) : "l"(p));
    return a;
}
__device__ __forceinline__ void cp16(void* smem_dst, const void* gmem_src) {
    unsigned s = (unsigned)__cvta_generic_to_shared(smem_dst);
    asm volatile("cp.async.cg.shared.global [%0], [%1], 16;\n" :: "r"(s), "l"(gmem_src));
}
__device__ __forceinline__ void cp_commit() { asm volatile("cp.async.commit_group;\n"); }
template <int N>
__device__ __forceinline__ void cp_wait() { asm volatile("cp.async.wait_group %0;\n" :: "n"(N)); }

__device__ __forceinline__ void ldsm4(unsigned* r, uint32_t addr) {
    asm volatile("ldmatrix.sync.aligned.m8n8.x4.shared.b16 {%0,%1,%2,%3}, [%4];"
                 : "=r"(r[0]), "=r"(r[1]), "=r"(r[2]), "=r"(r[3]) : "r"(addr));
}
__device__ __forceinline__ void ldsm4t(unsigned* r, uint32_t addr) {
    asm volatile("ldmatrix.sync.aligned.m8n8.x4.trans.shared.b16 {%0,%1,%2,%3}, [%4];"
                 : "=r"(r[0]), "=r"(r[1]), "=r"(r[2]), "=r"(r[3]) : "r"(addr));
}
__device__ __forceinline__ void mma_f16(float* d, const unsigned* a, const unsigned* b) {
    asm volatile(
        "mma.sync.aligned.m16n8k16.row.col.f32.f16.f16.f32 "
        "{%0,%1,%2,%3}, {%4,%5,%6,%7}, {%8,%9}, {%0,%1,%2,%3};\n"
        : "+f"(d[0]), "+f"(d[1]), "+f"(d[2]), "+f"(d[3])
        : "r"(a[0]), "r"(a[1]), "r"(a[2]), "r"(a[3]),
          "r"(b[0]), "r"(b[1]));
}
__device__ __forceinline__ unsigned pack_h2(float a, float b) {
    __half2 h = __floats2half2_rn(a, b);
    return *(unsigned*)&h;
}

// ---------------------------------------------------------------------------
// Merged pre-pass: fp32 -> fp16 for x, Wqkv, Wout in ONE launch.
// ---------------------------------------------------------------------------
#define N4X (MR * DD / 4)            // 2,097,152
#define N4Q (3 * DD * DD / 4)        //   786,432
#define N4O (DD * DD / 4)            //   262,144
#define N4TOT (N4X + N4Q + N4O)

__global__ void f2h_all(const float4* __restrict__ x,
                        const float4* __restrict__ wq,
                        const float4* __restrict__ wo)
{
    int i = blockIdx.x * blockDim.x + threadIdx.x;
    if (i >= N4TOT) return;
    const float4* src;
    uint2* dst;
    int off;
    if (i < N4X)            { src = x;  dst = (uint2*)g_Xh;    off = i; }
    else if (i < N4X + N4Q) { src = wq; dst = (uint2*)g_Wqkvh; off = i - N4X; }
    else                    { src = wo; dst = (uint2*)g_Wouth; off = i - N4X - N4Q; }
    float4 v = src[off];
    __half2 h0 = __floats2half2_rn(v.x, v.y);
    __half2 h1 = __floats2half2_rn(v.z, v.w);
    dst[off] = make_uint2(*(unsigned*)&h0, *(unsigned*)&h1);
}

// ---------------------------------------------------------------------------
// fp16 tensor-core GEMM (round-11 winner, unchanged): C[M,N]=A[M,K]*B[N,K]^T.
// CTA 128x128, BK=64, 8 warps, warp 64x32, ldmatrix.x4, 3-stage cp.async,
// one barrier per k-iteration. 110.6 KB smem, 128 regs -> 2 CTAs/SM.
// MODE 0: fp16 scatter into g_Qh/g_Kh/g_Vh; MODE 1: fp32 row-major C.
// ---------------------------------------------------------------------------
#define ROWH   72
#define TILE_H (128 * ROWH)
#define STAGE_H (2 * TILE_H)
#define NSTG   3
#define GEMM_SMEM (NSTG * STAGE_H * 2)     // 110592 B

template <int MODE>
__global__ __launch_bounds__(256, 2)
void mm_f16(const __half* __restrict__ A, const __half* __restrict__ Bm,
            float* __restrict__ C, int Kdim, int Ndim)
{
    extern __shared__ __half smh[];
    const uint32_t smem_base = smem_u32(smh);

    const int m0 = blockIdx.y * 128;
    const int n0 = blockIdx.x * 128;
    const int t  = threadIdx.x;
    const int warp = t >> 5, lane = t & 31;
    const int wm = (warp >> 2) * 64;
    const int wn = (warp & 3) * 32;
    const int g = lane >> 2;
    const int q = lane & 3;

    float acc[4][4][4];
#pragma unroll
    for (int i = 0; i < 4; i++)
#pragma unroll
        for (int j = 0; j < 4; j++)
#pragma unroll
            for (int r = 0; r < 4; r++) acc[i][j][r] = 0.f;

    const uint32_t a_off = (uint32_t)((wm + (lane & 15)) * ROWH + (lane >> 4) * 8) * 2;
    const uint32_t b_off = (uint32_t)((wn + (lane & 7) + ((lane >> 4) << 3)) * ROWH
                                      + ((lane >> 3) & 1) * 8) * 2;

    const int KT = Kdim >> 6;

    auto prefetch = [&](int kt, int s) {
        __half* As = smh + s * STAGE_H;
        __half* Bs = As + TILE_H;
        const int k0 = kt << 6;
#pragma unroll
        for (int u = 0; u < 4; u++) {
            int idx = t + u * 256;
            int row = idx >> 3, c8 = (idx & 7) << 3;
            cp16(As + row * ROWH + c8, A + (size_t)(m0 + row) * Kdim + k0 + c8);
        }
#pragma unroll
        for (int u = 0; u < 4; u++) {
            int idx = t + u * 256;
            int row = idx >> 3, c8 = (idx & 7) << 3;
            cp16(Bs + row * ROWH + c8, Bm + (size_t)(n0 + row) * Kdim + k0 + c8);
        }
    };

    prefetch(0, 0); cp_commit();
    prefetch(1, 1); cp_commit();

    int sbuf = 0;
    for (int kt = 0; kt < KT; kt++) {
        if (kt + 1 < KT) cp_wait<1>();
        else             cp_wait<0>();
        __syncthreads();

        if (kt + 2 < KT) {
            int s2 = sbuf + 2; if (s2 >= NSTG) s2 -= NSTG;
            prefetch(kt + 2, s2);
            cp_commit();
        }

        const uint32_t As_u = smem_base + (uint32_t)(sbuf * STAGE_H) * 2;
        const uint32_t Bs_u = As_u + TILE_H * 2;

#pragma unroll
        for (int ks = 0; ks < 4; ks++) {
            unsigned af[4][4], bf[2][4];
            const uint32_t kboff = (uint32_t)(ks * 16) * 2;
#pragma unroll
            for (int mi = 0; mi < 4; mi++)
                ldsm4(af[mi], As_u + a_off + kboff + (uint32_t)(mi * 16 * ROWH) * 2);
#pragma unroll
            for (int np = 0; np < 2; np++)
                ldsm4(bf[np], Bs_u + b_off + kboff + (uint32_t)(np * 16 * ROWH) * 2);
#pragma unroll
            for (int mi = 0; mi < 4; mi++)
#pragma unroll
                for (int ni = 0; ni < 4; ni++)
                    mma_f16(acc[mi][ni], af[mi], &bf[ni >> 1][(ni & 1) * 2]);
        }
        sbuf++; if (sbuf >= NSTG) sbuf = 0;
    }

#pragma unroll
    for (int mi = 0; mi < 4; mi++) {
        int mA = m0 + wm + mi * 16 + g;
#pragma unroll
        for (int ni = 0; ni < 4; ni++) {
            int n = n0 + wn + ni * 8 + 2 * q;
            if (MODE == 1) {
                float2 v0 = make_float2(acc[mi][ni][0], acc[mi][ni][1]);
                float2 v1 = make_float2(acc[mi][ni][2], acc[mi][ni][3]);
                *(float2*)(C + (size_t)mA * Ndim + n) = v0;
                *(float2*)(C + (size_t)(mA + 8) * Ndim + n) = v1;
            } else {
                int sel = n >> 10;
                int h   = (n >> 6) & (NH - 1);
                int hd  = n & (HDIM - 1);
                __half* dst = (sel == 0) ? g_Qh : (sel == 1) ? g_Kh : g_Vh;
                int b0r = mA >> 12, l0 = mA & (LL - 1);
                int b1r = (mA + 8) >> 12, l1 = (mA + 8) & (LL - 1);
                __half2 h0 = __floats2half2_rn(acc[mi][ni][0], acc[mi][ni][1]);
                __half2 h1 = __floats2half2_rn(acc[mi][ni][2], acc[mi][ni][3]);
                *(__half2*)(dst + ((size_t)(b0r * NH + h) * LL + l0) * HDIM + hd) = h0;
                *(__half2*)(dst + ((size_t)(b1r * NH + h) * LL + l1) * HDIM + hd) = h1;
            }
        }
    }
}

// ---------------------------------------------------------------------------
// Tensor-core block-local causal flash attention + fused RoPE.
// LOAD-BALANCED: warp w owns 16-row tiles t0=w and t1=15-w (9 chunks each).
// RoPE angles via multiplicative recurrence (1 __expf instead of 32).
// ---------------------------------------------------------------------------
#define AROW 72
#define ATILE (BSZ * AROW)                 // halves (18432)
#define ATTN_SMEM (3 * ATILE * 2)          // 110592 B

__global__ __launch_bounds__(256, 1)
void attn_tc()
{
    extern __shared__ __half sh[];
    __half* Qs = sh;
    __half* Ks = sh + ATILE;
    __half* Vs = sh + 2 * ATILE;
    const uint32_t Qs_u = smem_u32(Qs);
    const uint32_t Ks_u = Qs_u + ATILE * 2;
    const uint32_t Vs_u = Qs_u + 2 * ATILE * 2;

    const int cta = blockIdx.x;
    const int nb  = cta & (NBLK - 1);
    const int bh  = cta >> 4;
    const int b   = bh >> 4, h = bh & (NH - 1);
    const size_t rowbase = (size_t)bh * LL + (size_t)nb * BSZ;

    const int t = threadIdx.x;
    const int warp = t >> 5, lane = t & 31;
    const int g  = lane >> 2;
    const int q2 = (lane & 3) * 2;

    {
        const __half* Qg = g_Qh + rowbase * HDIM;
        const __half* Kg = g_Kh + rowbase * HDIM;
        const __half* Vg = g_Vh + rowbase * HDIM;
        for (int idx = t; idx < BSZ * HDIM / 8; idx += 256) {
            int row = idx >> 3, c8 = (idx & 7) << 3;
            cp16(Qs + row * AROW + c8, Qg + row * HDIM + c8);
            cp16(Ks + row * AROW + c8, Kg + row * HDIM + c8);
            cp16(Vs + row * AROW + c8, Vg + row * HDIM + c8);
        }
        cp_commit(); cp_wait<0>();
        __syncthreads();
    }

    // RoPE in-smem: read full row to regs first, then write (no overlap).
    {
        const int row = t;
        const float pos = (float)(nb * BSZ + row);
        const float r = __expf(-9.210340371976184f / 32.0f);  // 10000^(-1/32)
        float cs[32], sn[32];
        float freq = 1.0f;
#pragma unroll
        for (int i = 0; i < 32; i++) {
            __sincosf(pos * freq, &sn[i], &cs[i]);
            freq *= r;
        }
#pragma unroll
        for (int pass = 0; pass < 2; pass++) {
            __half* p = (pass == 0 ? Qs : Ks) + row * AROW;
            float xv[64];
#pragma unroll
            for (int d = 0; d < 32; d++) {
                __half2 v = ((__half2*)p)[d];
                xv[2 * d]     = __half2float(v.x);
                xv[2 * d + 1] = __half2float(v.y);
            }
#pragma unroll
            for (int i = 0; i < 32; i += 2) {
                *(__half2*)(p + i) = __floats2half2_rn(
                    xv[2 * i]     * cs[i]     - xv[2 * i + 1] * sn[i],
                    xv[2 * i + 2] * cs[i + 1] - xv[2 * i + 3] * sn[i + 1]);
                *(__half2*)(p + 32 + i) = __floats2half2_rn(
                    xv[2 * i + 1] * cs[i]     + xv[2 * i]     * sn[i],
                    xv[2 * i + 3] * cs[i + 1] + xv[2 * i + 2] * sn[i + 1]);
            }
        }
        __syncthreads();
    }

    const int tt[2] = { warp, 15 - warp };
    const int Ct[2] = { warp / 2 + 1, (15 - warp) / 2 + 1 };
    const int Cmax = Ct[1];

    unsigned qf[2][4][4];
#pragma unroll
    for (int mt = 0; mt < 2; mt++)
#pragma unroll
        for (int ks = 0; ks < 4; ks++)
            ldsm4(qf[mt][ks], Qs_u + (uint32_t)(((tt[mt] * 16 + (lane & 15)) * AROW
                                                 + ks * 16 + (lane >> 4) * 8) * 2));

    float o[2][8][4];
#pragma unroll
    for (int mt = 0; mt < 2; mt++)
#pragma unroll
        for (int nd = 0; nd < 8; nd++)
#pragma unroll
            for (int e = 0; e < 4; e++) o[mt][nd][e] = 0.f;

    float mrow[2][2] = {{-1e30f, -1e30f}, {-1e30f, -1e30f}};
    float lrow[2][2] = {{0.f, 0.f}, {0.f, 0.f}};

    for (int c = 0; c < Cmax; c++) {
        unsigned bk[4][2][4];
#pragma unroll
        for (int ks = 0; ks < 4; ks++) {
            uint32_t base = Ks_u + (uint32_t)(((c * 32 + (lane & 7) + ((lane >> 4) << 3)) * AROW
                                               + ks * 16 + ((lane >> 3) & 1) * 8) * 2);
            ldsm4(bk[ks][0], base);
            ldsm4(bk[ks][1], base + (uint32_t)(16 * AROW * 2));
        }

        float s[2][4][4];
#pragma unroll
        for (int mt = 0; mt < 2; mt++) {
            if (c >= Ct[mt]) continue;
#pragma unroll
            for (int nt = 0; nt < 4; nt++)
#pragma unroll
                for (int e = 0; e < 4; e++) s[mt][nt][e] = 0.f;
#pragma unroll
            for (int ks = 0; ks < 4; ks++) {
                mma_f16(s[mt][0], qf[mt][ks], &bk[ks][0][0]);
                mma_f16(s[mt][1], qf[mt][ks], &bk[ks][0][2]);
                mma_f16(s[mt][2], qf[mt][ks], &bk[ks][1][0]);
                mma_f16(s[mt][3], qf[mt][ks], &bk[ks][1][2]);
            }

#pragma unroll
            for (int nt = 0; nt < 4; nt++)
#pragma unroll
                for (int e = 0; e < 4; e++) s[mt][nt][e] *= 0.125f;

            if (c == Ct[mt] - 1) {
                const int rA = tt[mt] * 16 + g, rB = rA + 8;
#pragma unroll
                for (int nt = 0; nt < 4; nt++) {
                    int colg = 32 * c + 8 * nt + q2;
                    if (colg     > rA) s[mt][nt][0] = -1e30f;
                    if (colg + 1 > rA) s[mt][nt][1] = -1e30f;
                    if (colg     > rB) s[mt][nt][2] = -1e30f;
                    if (colg + 1 > rB) s[mt][nt][3] = -1e30f;
                }
            }

            float mxA = -1e30f, mxB = -1e30f;
#pragma unroll
            for (int nt = 0; nt < 4; nt++) {
                mxA = fmaxf(mxA, fmaxf(s[mt][nt][0], s[mt][nt][1]));
                mxB = fmaxf(mxB, fmaxf(s[mt][nt][2], s[mt][nt][3]));
            }
            mxA = fmaxf(mxA, __shfl_xor_sync(0xFFFFFFFFu, mxA, 1));
            mxA = fmaxf(mxA, __shfl_xor_sync(0xFFFFFFFFu, mxA, 2));
            mxB = fmaxf(mxB, __shfl_xor_sync(0xFFFFFFFFu, mxB, 1));
            mxB = fmaxf(mxB, __shfl_xor_sync(0xFFFFFFFFu, mxB, 2));

            float newA = fmaxf(mrow[mt][0], mxA);
            float newB = fmaxf(mrow[mt][1], mxB);
            float fA = __expf(mrow[mt][0] - newA);
            float fB = __expf(mrow[mt][1] - newB);
            mrow[mt][0] = newA; mrow[mt][1] = newB;

            float sumA = 0.f, sumB = 0.f;
#pragma unroll
            for (int nt = 0; nt < 4; nt++) {
                s[mt][nt][0] = __expf(s[mt][nt][0] - newA);
                s[mt][nt][1] = __expf(s[mt][nt][1] - newA);
                s[mt][nt][2] = __expf(s[mt][nt][2] - newB);
                s[mt][nt][3] = __expf(s[mt][nt][3] - newB);
                sumA += s[mt][nt][0] + s[mt][nt][1];
                sumB += s[mt][nt][2] + s[mt][nt][3];
            }
            sumA += __shfl_xor_sync(0xFFFFFFFFu, sumA, 1);
            sumA += __shfl_xor_sync(0xFFFFFFFFu, sumA, 2);
            sumB += __shfl_xor_sync(0xFFFFFFFFu, sumB, 1);
            sumB += __shfl_xor_sync(0xFFFFFFFFu, sumB, 2);
            lrow[mt][0] = lrow[mt][0] * fA + sumA;
            lrow[mt][1] = lrow[mt][1] * fB + sumB;

#pragma unroll
            for (int nd = 0; nd < 8; nd++) {
                o[mt][nd][0] *= fA; o[mt][nd][1] *= fA;
                o[mt][nd][2] *= fB; o[mt][nd][3] *= fB;
            }
        }

#pragma unroll
        for (int pt = 0; pt < 2; pt++) {
            unsigned vb[4][4];
#pragma unroll
            for (int nd16 = 0; nd16 < 4; nd16++) {
                uint32_t addr = Vs_u + (uint32_t)(((c * 32 + pt * 16 + (lane & 7)
                                                   + (((lane >> 3) & 1) << 3)) * AROW
                                                  + nd16 * 16 + (lane >> 4) * 8) * 2);
                ldsm4t(vb[nd16], addr);
            }
#pragma unroll
            for (int mt = 0; mt < 2; mt++) {
                if (c >= Ct[mt]) continue;
                unsigned pa[4];
                pa[0] = pack_h2(s[mt][2 * pt][0],     s[mt][2 * pt][1]);
                pa[1] = pack_h2(s[mt][2 * pt][2],     s[mt][2 * pt][3]);
                pa[2] = pack_h2(s[mt][2 * pt + 1][0], s[mt][2 * pt + 1][1]);
                pa[3] = pack_h2(s[mt][2 * pt + 1][2], s[mt][2 * pt + 1][3]);
#pragma unroll
                for (int nd16 = 0; nd16 < 4; nd16++) {
                    mma_f16(o[mt][2 * nd16],     pa, &vb[nd16][0]);
                    mma_f16(o[mt][2 * nd16 + 1], pa, &vb[nd16][2]);
                }
            }
        }
    }

#pragma unroll
    for (int mt = 0; mt < 2; mt++) {
        float iA = 1.f / lrow[mt][0];
        float iB = 1.f / lrow[mt][1];
        const int rA = tt[mt] * 16 + g;
        size_t baseA = ((size_t)(b * LL) + nb * BSZ + rA) * DD + h * HDIM;
        size_t baseB = baseA + (size_t)8 * DD;
#pragma unroll
        for (int nd = 0; nd < 8; nd++) {
            *(__half2*)(g_Oh + baseA + 8 * nd + q2) =
                __floats2half2_rn(o[mt][nd][0] * iA, o[mt][nd][1] * iA);
            *(__half2*)(g_Oh + baseB + 8 * nd + q2) =
                __floats2half2_rn(o[mt][nd][2] * iB, o[mt][nd][3] * iB);
        }
    }
}

// ---------------------------------------------------------------------------
extern "C" void kernel_launch(void* const* d_in, const int* in_sizes, int n_in,
                              void* d_out, int out_size)
{
    const float* x    = (const float*)d_in[0];
    const float* Wqkv = (const float*)d_in[1];
    const float* Wout = (const float*)d_in[2];
    float* out = (float*)d_out;

    void *Oh = nullptr, *Xh = nullptr, *Wqh = nullptr, *Woh = nullptr;
    cudaGetSymbolAddress(&Oh, g_Oh);
    cudaGetSymbolAddress(&Xh, g_Xh);
    cudaGetSymbolAddress(&Wqh, g_Wqkvh);
    cudaGetSymbolAddress(&Woh, g_Wouth);

    cudaFuncSetAttribute(mm_f16<0>, cudaFuncAttributeMaxDynamicSharedMemorySize, GEMM_SMEM);
    cudaFuncSetAttribute(mm_f16<1>, cudaFuncAttributeMaxDynamicSharedMemorySize, GEMM_SMEM);
    cudaFuncSetAttribute(attn_tc, cudaFuncAttributeMaxDynamicSharedMemorySize, ATTN_SMEM);

    // 0) fp32 -> fp16 conversion of x, Wqkv, Wout (single launch)
    f2h_all<<<(N4TOT + 255) / 256, 256>>>((const float4*)x, (const float4*)Wqkv,
                                          (const float4*)Wout);

    // 1) QKV projection (fp16 tensor cores) -> fp16 Q/K/V in [B,H,L,HD]
    mm_f16<0><<<dim3(3 * DD / 128, MR / 128), 256, GEMM_SMEM>>>(
        (const __half*)Xh, (const __half*)Wqh, nullptr, DD, 3 * DD);

    // 2) Fused RoPE + balanced tensor-core flash attention -> g_Oh fp16 [B,L,D]
    attn_tc<<<BB * NH * NBLK, 256, ATTN_SMEM>>>();

    // 3) Output projection (fp16 tensor cores) -> fp32 out
    mm_f16<1><<<dim3(DD / 128, MR / 128), 256, GEMM_SMEM>>>(
        (const __half*)Oh, (const __half*)Woh, out, DD, DD);
}